// round 14
// baseline (speedup 1.0000x reference)
#include <cuda_runtime.h>
#include <cuda_bf16.h>
#include <cuda_fp16.h>
#include <math.h>
#include <stdint.h>

#define N_NODES 50000
#define N_EDGES 1600000
#define IN_FEATS 256
#define HF 128           // N_HEADS * OUT_FEATS
#define NEG_SLOPE 0.2f
#define EDGE_STRIDE 192  // fixed bucket per node (Poisson(32): P(deg>192) ~ e^-150)
#define BLOCK_M 64

// -------- device scratch --------
__device__ __half g_fth[(size_t)N_NODES * HF];    // projected features fp16
__device__ float g_el[N_NODES * 2];
__device__ float g_er[N_NODES * 2];
__device__ int   g_deg[N_NODES];                  // zero at every call entry (invariant)
__device__ int   g_ssrc[(size_t)N_NODES * EDGE_STRIDE];  // padded per-dst buckets

// ===========================================================================
// helpers
// ===========================================================================
__device__ __forceinline__ uint32_t smem_u32(const void* p) {
    uint32_t a;
    asm("{ .reg .u64 t; cvta.to.shared.u64 t, %1; cvt.u32.u64 %0, t; }" : "=r"(a) : "l"(p));
    return a;
}
__device__ __forceinline__ void ldsm4(uint32_t* r, uint32_t addr) {
    asm volatile("ldmatrix.sync.aligned.m8n8.x4.shared.b16 {%0,%1,%2,%3}, [%4];"
                 : "=r"(r[0]), "=r"(r[1]), "=r"(r[2]), "=r"(r[3]) : "r"(addr));
}
__device__ __forceinline__ void mma16816(float* d, const uint32_t* a, const uint32_t* b) {
    asm volatile("mma.sync.aligned.m16n8k16.row.col.f32.bf16.bf16.f32 "
                 "{%0,%1,%2,%3}, {%4,%5,%6,%7}, {%8,%9}, {%0,%1,%2,%3};"
                 : "+f"(d[0]), "+f"(d[1]), "+f"(d[2]), "+f"(d[3])
                 : "r"(a[0]), "r"(a[1]), "r"(a[2]), "r"(a[3]), "r"(b[0]), "r"(b[1]));
}

// smem: per-buffer layout (48 KB), two buffers (double-buffered K chunks)
#define AHI 0
#define ALO 8192
#define BHI 16384
#define BLO 32768
#define BUFSZ 49152
#define SM_TOTAL (2 * BUFSZ)

// load + bf16-split one 64-wide K chunk (A: 64 rows, B: 128 cols)
__device__ __forceinline__ void load_chunk(const float* __restrict__ A,
                                           const float* __restrict__ W,
                                           int m0, int M, int tid, int kc,
                                           char* sbuf) {
    #pragma unroll
    for (int i = 0; i < 8; i++) {
        int idx = tid + i * 256;          // 2048 = 64 rows x 32 kpairs
        int row = idx >> 5, kp = idx & 31;
        int gr = m0 + row;
        float2 a = (gr < M) ? __ldcs((const float2*)(A + (size_t)gr * IN_FEATS + kc + kp * 2))
                            : make_float2(0.f, 0.f);
        __nv_bfloat16 hx = __float2bfloat16(a.x), hy = __float2bfloat16(a.y);
        float lx = a.x - __bfloat162float(hx), ly = a.y - __bfloat162float(hy);
        uint32_t off = row * 128 + ((kp * 4) ^ ((row & 7) << 4));
        *(__nv_bfloat162*)(sbuf + AHI + off) = __halves2bfloat162(hx, hy);
        *(__nv_bfloat162*)(sbuf + ALO + off) =
            __halves2bfloat162(__float2bfloat16(lx), __float2bfloat16(ly));
    }
    #pragma unroll
    for (int i = 0; i < 32; i++) {
        int idx = tid + i * 256;          // 8192 = 64 k x 128 n
        int kr = idx >> 7, n = idx & 127;
        float b = __ldg(W + (size_t)(kc + kr) * HF + n);
        __nv_bfloat16 h = __float2bfloat16(b);
        float l = b - __bfloat162float(h);
        uint32_t off = n * 128 + ((kr * 2) ^ ((n & 7) << 4));
        *(__nv_bfloat16*)(sbuf + BHI + off) = h;
        *(__nv_bfloat16*)(sbuf + BLO + off) = __float2bfloat16(l);
    }
}

// ===========================================================================
// Kernel 1: bf16-split mma.sync GEMM, M-tile 64, 2 CTAs/SM, double-buffered
// warp layout: 4 row-warps x 16 M, 2 col-warps x 64 N (one head per col-warp)
// ===========================================================================
__global__ void __launch_bounds__(256, 2)
gemm_mma(const float* __restrict__ A, const float* __restrict__ W,
         const float* __restrict__ al, const float* __restrict__ ar_,
         __half* __restrict__ fth, float* __restrict__ el, float* __restrict__ er,
         int M) {
    extern __shared__ char smem[];
    const uint32_t sb = smem_u32(smem);
    const int tid = threadIdx.x;
    const int wid = tid >> 5;
    const int lane = tid & 31;
    const int warpRow = wid & 3;    // 4 row-warps of 16 M
    const int warpCol = wid >> 2;   // 2 col-warps of 64 N
    const int m0 = blockIdx.x * BLOCK_M;

    float acc[8][4];
    #pragma unroll
    for (int b = 0; b < 8; b++)
        #pragma unroll
        for (int c = 0; c < 4; c++) acc[b][c] = 0.f;

    load_chunk(A, W, m0, M, tid, 0, smem);
    __syncthreads();

    for (int c = 0; c < 4; c++) {
        const uint32_t sbc = sb + (c & 1) * BUFSZ;
        if (c < 3)
            load_chunk(A, W, m0, M, tid, (c + 1) * 64, smem + ((c + 1) & 1) * BUFSZ);

        #pragma unroll
        for (int ks = 0; ks < 4; ks++) {
            uint32_t ahi[4], alo[4], bh[8][2], bl[8][2];
            {
                int row = warpRow * 16 + (lane & 15);
                int kb = ks * 32 + ((lane >> 4) << 4);
                uint32_t off = row * 128 + (kb ^ ((row & 7) << 4));
                ldsm4(ahi, sbc + AHI + off);
                ldsm4(alo, sbc + ALO + off);
            }
            #pragma unroll
            for (int tp = 0; tp < 4; tp++) {
                int n = warpCol * 64 + tp * 16 + ((lane >> 4) << 3) + (lane & 7);
                int kb = ks * 32 + (((lane >> 3) & 1) << 4);
                uint32_t off = n * 128 + (kb ^ ((n & 7) << 4));
                uint32_t r[4];
                ldsm4(r, sbc + BHI + off);
                bh[tp * 2][0] = r[0]; bh[tp * 2][1] = r[1];
                bh[tp * 2 + 1][0] = r[2]; bh[tp * 2 + 1][1] = r[3];
                ldsm4(r, sbc + BLO + off);
                bl[tp * 2][0] = r[0]; bl[tp * 2][1] = r[1];
                bl[tp * 2 + 1][0] = r[2]; bl[tp * 2 + 1][1] = r[3];
            }
            #pragma unroll
            for (int tn = 0; tn < 8; tn++) {
                mma16816(acc[tn], ahi, bh[tn]);
                mma16816(acc[tn], ahi, bl[tn]);
                mma16816(acc[tn], alo, bh[tn]);
            }
        }
        __syncthreads();
    }

    // ---- epilogue: fp16 store + fused per-head attention dots ----
    const int qr = lane >> 2, qc = lane & 3;
    #pragma unroll
    for (int h = 0; h < 2; h++) {
        int row = m0 + warpRow * 16 + 8 * h + qr;
        float dotl = 0.f, dotr = 0.f;
        #pragma unroll
        for (int tn = 0; tn < 8; tn++) {
            float v0 = acc[tn][2 * h + 0];
            float v1 = acc[tn][2 * h + 1];
            int col = warpCol * 64 + tn * 8 + qc * 2;
            dotl = fmaf(v0, __ldg(al + col), fmaf(v1, __ldg(al + col + 1), dotl));
            dotr = fmaf(v0, __ldg(ar_ + col), fmaf(v1, __ldg(ar_ + col + 1), dotr));
            if (row < M)
                *(__half2*)(fth + (size_t)row * HF + col) = __floats2half2_rn(v0, v1);
        }
        dotl += __shfl_xor_sync(0xffffffffu, dotl, 1);
        dotl += __shfl_xor_sync(0xffffffffu, dotl, 2);
        dotr += __shfl_xor_sync(0xffffffffu, dotr, 1);
        dotr += __shfl_xor_sync(0xffffffffu, dotr, 2);
        if (qc == 0 && row < M) {
            el[row * 2 + warpCol] = dotl;
            er[row * 2 + warpCol] = dotr;
        }
    }
}

// ===========================================================================
// ONE-pass CSR build into padded buckets.
// ===========================================================================
__global__ void __launch_bounds__(256)
hist_scatter(const int4* __restrict__ src4, const int4* __restrict__ dst4) {
    int i = blockIdx.x * blockDim.x + threadIdx.x;
    if (i < N_EDGES / 4) {
        int4 s = __ldcs(src4 + i);
        int4 d = __ldcs(dst4 + i);
        int r;
        r = atomicAdd(&g_deg[d.x], 1); __stcs(&g_ssrc[(size_t)d.x * EDGE_STRIDE + r], s.x);
        r = atomicAdd(&g_deg[d.y], 1); __stcs(&g_ssrc[(size_t)d.y * EDGE_STRIDE + r], s.y);
        r = atomicAdd(&g_deg[d.z], 1); __stcs(&g_ssrc[(size_t)d.z * EDGE_STRIDE + r], s.z);
        r = atomicAdd(&g_deg[d.w], 1); __stcs(&g_ssrc[(size_t)d.w * EDGE_STRIDE + r], s.w);
    }
}

// ===========================================================================
// warp-per-node softmax + aggregation; resets g_deg afterward.
// ===========================================================================
__global__ void gat_agg(float* __restrict__ out) {
    int gtid = blockIdx.x * blockDim.x + threadIdx.x;
    int node = gtid >> 5;
    int lane = gtid & 31;
    if (node >= N_NODES) return;

    const int deg = g_deg[node];
    const int beg = node * EDGE_STRIDE;
    const int end = beg + deg;
    const float er0 = g_er[node * 2 + 0];
    const float er1 = g_er[node * 2 + 1];
    const int half16 = lane >> 4;
    const int l16 = lane & 15;
    const int head = l16 >> 3;

    const uint4* ftp = (const uint4*)g_fth;
    float acc[8];
    #pragma unroll
    for (int j = 0; j < 8; j++) acc[j] = 0.f;
    float s0 = 0.f, s1 = 0.f;

    for (int cb = beg; cb < end; cb += 32) {
        int i = cb + lane;
        float p0 = 0.f, p1 = 0.f;
        int sv = 0;
        if (i < end) {
            sv = __ldcs(g_ssrc + i);
            float2 elv = *(const float2*)(g_el + 2 * sv);
            float e0 = elv.x + er0; e0 = fmaxf(e0, NEG_SLOPE * e0);
            float e1 = elv.y + er1; e1 = fmaxf(e1, NEG_SLOPE * e1);
            p0 = __expf(e0);
            p1 = __expf(e1);
        }
        s0 += p0; s1 += p1;
        int cnt = min(32, end - cb);
        #pragma unroll 4
        for (int e = 0; e < cnt; e += 2) {
            int eA = e + half16;
            bool valid = eA < cnt;
            int esel = valid ? eA : 0;
            int   ss  = __shfl_sync(0xffffffffu, sv, esel);
            float pp0 = __shfl_sync(0xffffffffu, p0, esel);
            float pp1 = __shfl_sync(0xffffffffu, p1, esel);
            float pp = head ? pp1 : pp0;
            if (!valid) pp = 0.f;
            uint4 v = ftp[(size_t)ss * 16 + l16];
            float2 f0 = __half22float2(*(__half2*)&v.x);
            float2 f1 = __half22float2(*(__half2*)&v.y);
            float2 f2 = __half22float2(*(__half2*)&v.z);
            float2 f3 = __half22float2(*(__half2*)&v.w);
            acc[0] = fmaf(pp, f0.x, acc[0]);
            acc[1] = fmaf(pp, f0.y, acc[1]);
            acc[2] = fmaf(pp, f1.x, acc[2]);
            acc[3] = fmaf(pp, f1.y, acc[3]);
            acc[4] = fmaf(pp, f2.x, acc[4]);
            acc[5] = fmaf(pp, f2.y, acc[5]);
            acc[6] = fmaf(pp, f3.x, acc[6]);
            acc[7] = fmaf(pp, f3.y, acc[7]);
        }
    }

    #pragma unroll
    for (int j = 0; j < 8; j++)
        acc[j] += __shfl_xor_sync(0xffffffffu, acc[j], 16);

    #pragma unroll
    for (int d = 16; d; d >>= 1) {
        s0 += __shfl_xor_sync(0xffffffffu, s0, d);
        s1 += __shfl_xor_sync(0xffffffffu, s1, d);
    }
    float inv = 1.f / fmaxf(head ? s1 : s0, 1e-20f);

    if (half16 == 0) {
        float4* op = (float4*)(out + (size_t)node * HF + l16 * 8);
        __stcs(op,     make_float4(acc[0] * inv, acc[1] * inv, acc[2] * inv, acc[3] * inv));
        __stcs(op + 1, make_float4(acc[4] * inv, acc[5] * inv, acc[6] * inv, acc[7] * inv));
    }
    if (lane == 0) g_deg[node] = 0;   // restore invariant for next call
}

// ===========================================================================
extern "C" void kernel_launch(void* const* d_in, const int* in_sizes, int n_in,
                              void* d_out, int out_size) {
    const float* feat   = (const float*)d_in[0];
    const int*   src    = (const int*)  d_in[1];
    const int*   dst    = (const int*)  d_in[2];
    const float* W      = (const float*)d_in[3];
    const float* attn_l = (const float*)d_in[4];
    const float* attn_r = (const float*)d_in[5];
    float* out = (float*)d_out;

    __half* fth_p; cudaGetSymbolAddress((void**)&fth_p, g_fth);
    float*  el_p;  cudaGetSymbolAddress((void**)&el_p, g_el);
    float*  er_p;  cudaGetSymbolAddress((void**)&er_p, g_er);

    cudaFuncSetAttribute(gemm_mma, cudaFuncAttributeMaxDynamicSharedMemorySize, SM_TOTAL);

    static cudaStream_t s1 = [] {
        cudaStream_t s; cudaStreamCreateWithFlags(&s, cudaStreamNonBlocking); return s;
    }();
    static cudaEvent_t e0 = [] {
        cudaEvent_t e; cudaEventCreateWithFlags(&e, cudaEventDisableTiming); return e;
    }();
    static cudaEvent_t e1 = [] {
        cudaEvent_t e; cudaEventCreateWithFlags(&e, cudaEventDisableTiming); return e;
    }();

    // Fork: GEMM on s1 (independent of bucket build).
    cudaEventRecord(e0, 0);
    cudaStreamWaitEvent(s1, e0, 0);
    gemm_mma<<<(N_NODES + BLOCK_M - 1) / BLOCK_M, 256, SM_TOTAL, s1>>>(
        feat, W, attn_l, attn_r, fth_p, el_p, er_p, N_NODES);
    cudaEventRecord(e1, s1);

    // Main stream: single-pass bucket build (g_deg zero on entry by invariant).
    hist_scatter<<<(N_EDGES / 4 + 255) / 256, 256>>>((const int4*)src, (const int4*)dst);

    // Join, then aggregate.
    cudaStreamWaitEvent(0, e1, 0);
    gat_agg<<<(N_NODES * 32 + 255) / 256, 256>>>(out);
}

// round 15
// speedup vs baseline: 1.0916x; 1.0916x over previous
#include <cuda_runtime.h>
#include <cuda_bf16.h>
#include <cuda_fp16.h>
#include <math.h>
#include <stdint.h>

#define N_NODES 50000
#define N_EDGES 1600000
#define IN_FEATS 256
#define HF 128           // N_HEADS * OUT_FEATS
#define NEG_SLOPE 0.2f
#define EDGE_STRIDE 192  // fixed bucket per node (Poisson(32): P(deg>192) ~ e^-150)
#define BLOCK_M 128

// -------- device scratch --------
__device__ __half g_fth[(size_t)N_NODES * HF];    // projected features fp16
__device__ float g_el[N_NODES * 2];
__device__ float g_er[N_NODES * 2];
__device__ int   g_deg[N_NODES];                  // zero at every call entry (invariant)
__device__ int   g_ssrc[(size_t)N_NODES * EDGE_STRIDE];  // padded per-dst buckets

// ===========================================================================
// helpers
// ===========================================================================
__device__ __forceinline__ uint32_t smem_u32(const void* p) {
    uint32_t a;
    asm("{ .reg .u64 t; cvta.to.shared.u64 t, %1; cvt.u32.u64 %0, t; }" : "=r"(a) : "l"(p));
    return a;
}
__device__ __forceinline__ void ldsm4(uint32_t* r, uint32_t addr) {
    asm volatile("ldmatrix.sync.aligned.m8n8.x4.shared.b16 {%0,%1,%2,%3}, [%4];"
                 : "=r"(r[0]), "=r"(r[1]), "=r"(r[2]), "=r"(r[3]) : "r"(addr));
}
__device__ __forceinline__ void mma16816(float* d, const uint32_t* a, const uint32_t* b) {
    asm volatile("mma.sync.aligned.m16n8k16.row.col.f32.bf16.bf16.f32 "
                 "{%0,%1,%2,%3}, {%4,%5,%6,%7}, {%8,%9}, {%0,%1,%2,%3};"
                 : "+f"(d[0]), "+f"(d[1]), "+f"(d[2]), "+f"(d[3])
                 : "r"(a[0]), "r"(a[1]), "r"(a[2]), "r"(a[3]), "r"(b[0]), "r"(b[1]));
}

// smem: per-buffer layout (64 KB), two buffers (double-buffered K chunks)
#define AHI 0
#define ALO 16384
#define BHI 32768
#define BLO 49152
#define BUFSZ 65536
#define SM_TOTAL (2 * BUFSZ)

// load + bf16-split one 64-wide K chunk (A: 128 rows, B: 128 cols), 512 thr
__device__ __forceinline__ void load_chunk(const float* __restrict__ A,
                                           const float* __restrict__ W,
                                           int m0, int M, int tid, int kc,
                                           char* sbuf) {
    #pragma unroll
    for (int i = 0; i < 8; i++) {
        int idx = tid + i * 512;          // 4096 = 128 rows x 32 kpairs
        int row = idx >> 5, kp = idx & 31;
        int gr = m0 + row;
        float2 a = (gr < M) ? __ldcs((const float2*)(A + (size_t)gr * IN_FEATS + kc + kp * 2))
                            : make_float2(0.f, 0.f);
        __nv_bfloat16 hx = __float2bfloat16(a.x), hy = __float2bfloat16(a.y);
        float lx = a.x - __bfloat162float(hx), ly = a.y - __bfloat162float(hy);
        uint32_t off = row * 128 + ((kp * 4) ^ ((row & 7) << 4));
        *(__nv_bfloat162*)(sbuf + AHI + off) = __halves2bfloat162(hx, hy);
        *(__nv_bfloat162*)(sbuf + ALO + off) =
            __halves2bfloat162(__float2bfloat16(lx), __float2bfloat16(ly));
    }
    #pragma unroll
    for (int i = 0; i < 16; i++) {
        int idx = tid + i * 512;          // 8192 = 64 k x 128 n
        int kr = idx >> 7, n = idx & 127;
        float b = __ldg(W + (size_t)(kc + kr) * HF + n);
        __nv_bfloat16 h = __float2bfloat16(b);
        float l = b - __bfloat162float(h);
        uint32_t off = n * 128 + ((kr * 2) ^ ((n & 7) << 4));
        *(__nv_bfloat16*)(sbuf + BHI + off) = h;
        *(__nv_bfloat16*)(sbuf + BLO + off) = __float2bfloat16(l);
    }
}

// ===========================================================================
// Kernel 1: bf16-split mma.sync GEMM, M-tile 128, 512 threads (16 warps),
// double-buffered. Warp layout: 8 row-warps x 16 M, 2 col-warps x 64 N.
// ===========================================================================
__global__ void __launch_bounds__(512, 1)
gemm_mma(const float* __restrict__ A, const float* __restrict__ W,
         const float* __restrict__ al, const float* __restrict__ ar_,
         __half* __restrict__ fth, float* __restrict__ el, float* __restrict__ er,
         int M) {
    extern __shared__ char smem[];
    const uint32_t sb = smem_u32(smem);
    const int tid = threadIdx.x;
    const int wid = tid >> 5;
    const int lane = tid & 31;
    const int warpRow = wid & 7;    // 8 row-warps of 16 M
    const int warpCol = wid >> 3;   // 2 col-warps of 64 N (one head each)
    const int m0 = blockIdx.x * BLOCK_M;

    float acc[8][4];
    #pragma unroll
    for (int b = 0; b < 8; b++)
        #pragma unroll
        for (int c = 0; c < 4; c++) acc[b][c] = 0.f;

    load_chunk(A, W, m0, M, tid, 0, smem);
    __syncthreads();

    for (int c = 0; c < 4; c++) {
        const uint32_t sbc = sb + (c & 1) * BUFSZ;
        if (c < 3)
            load_chunk(A, W, m0, M, tid, (c + 1) * 64, smem + ((c + 1) & 1) * BUFSZ);

        #pragma unroll
        for (int ks = 0; ks < 4; ks++) {
            uint32_t ahi[4], alo[4], bh[8][2], bl[8][2];
            {
                int row = warpRow * 16 + (lane & 15);
                int kb = ks * 32 + ((lane >> 4) << 4);
                uint32_t off = row * 128 + (kb ^ ((row & 7) << 4));
                ldsm4(ahi, sbc + AHI + off);
                ldsm4(alo, sbc + ALO + off);
            }
            #pragma unroll
            for (int tp = 0; tp < 4; tp++) {
                int n = warpCol * 64 + tp * 16 + ((lane >> 4) << 3) + (lane & 7);
                int kb = ks * 32 + (((lane >> 3) & 1) << 4);
                uint32_t off = n * 128 + (kb ^ ((n & 7) << 4));
                uint32_t r[4];
                ldsm4(r, sbc + BHI + off);
                bh[tp * 2][0] = r[0]; bh[tp * 2][1] = r[1];
                bh[tp * 2 + 1][0] = r[2]; bh[tp * 2 + 1][1] = r[3];
                ldsm4(r, sbc + BLO + off);
                bl[tp * 2][0] = r[0]; bl[tp * 2][1] = r[1];
                bl[tp * 2 + 1][0] = r[2]; bl[tp * 2 + 1][1] = r[3];
            }
            #pragma unroll
            for (int tn = 0; tn < 8; tn++) {
                mma16816(acc[tn], ahi, bh[tn]);
                mma16816(acc[tn], ahi, bl[tn]);
                mma16816(acc[tn], alo, bh[tn]);
            }
        }
        __syncthreads();
    }

    // ---- epilogue: fp16 store + fused per-head attention dots ----
    const int qr = lane >> 2, qc = lane & 3;
    #pragma unroll
    for (int h = 0; h < 2; h++) {
        int row = m0 + warpRow * 16 + 8 * h + qr;
        float dotl = 0.f, dotr = 0.f;
        #pragma unroll
        for (int tn = 0; tn < 8; tn++) {
            float v0 = acc[tn][2 * h + 0];
            float v1 = acc[tn][2 * h + 1];
            int col = warpCol * 64 + tn * 8 + qc * 2;
            dotl = fmaf(v0, __ldg(al + col), fmaf(v1, __ldg(al + col + 1), dotl));
            dotr = fmaf(v0, __ldg(ar_ + col), fmaf(v1, __ldg(ar_ + col + 1), dotr));
            if (row < M)
                *(__half2*)(fth + (size_t)row * HF + col) = __floats2half2_rn(v0, v1);
        }
        dotl += __shfl_xor_sync(0xffffffffu, dotl, 1);
        dotl += __shfl_xor_sync(0xffffffffu, dotl, 2);
        dotr += __shfl_xor_sync(0xffffffffu, dotr, 1);
        dotr += __shfl_xor_sync(0xffffffffu, dotr, 2);
        if (qc == 0 && row < M) {
            el[row * 2 + warpCol] = dotl;
            er[row * 2 + warpCol] = dotr;
        }
    }
}

// ===========================================================================
// ONE-pass CSR build into padded buckets.
// ===========================================================================
__global__ void __launch_bounds__(256)
hist_scatter(const int4* __restrict__ src4, const int4* __restrict__ dst4) {
    int i = blockIdx.x * blockDim.x + threadIdx.x;
    if (i < N_EDGES / 4) {
        int4 s = __ldcs(src4 + i);
        int4 d = __ldcs(dst4 + i);
        int r;
        r = atomicAdd(&g_deg[d.x], 1); __stcs(&g_ssrc[(size_t)d.x * EDGE_STRIDE + r], s.x);
        r = atomicAdd(&g_deg[d.y], 1); __stcs(&g_ssrc[(size_t)d.y * EDGE_STRIDE + r], s.y);
        r = atomicAdd(&g_deg[d.z], 1); __stcs(&g_ssrc[(size_t)d.z * EDGE_STRIDE + r], s.z);
        r = atomicAdd(&g_deg[d.w], 1); __stcs(&g_ssrc[(size_t)d.w * EDGE_STRIDE + r], s.w);
    }
}

// ===========================================================================
// warp-per-node softmax + aggregation; resets g_deg afterward.
// ===========================================================================
__global__ void gat_agg(float* __restrict__ out) {
    int gtid = blockIdx.x * blockDim.x + threadIdx.x;
    int node = gtid >> 5;
    int lane = gtid & 31;
    if (node >= N_NODES) return;

    const int deg = g_deg[node];
    const int beg = node * EDGE_STRIDE;
    const int end = beg + deg;
    const float er0 = g_er[node * 2 + 0];
    const float er1 = g_er[node * 2 + 1];
    const int half16 = lane >> 4;
    const int l16 = lane & 15;
    const int head = l16 >> 3;

    const uint4* ftp = (const uint4*)g_fth;
    float acc[8];
    #pragma unroll
    for (int j = 0; j < 8; j++) acc[j] = 0.f;
    float s0 = 0.f, s1 = 0.f;

    for (int cb = beg; cb < end; cb += 32) {
        int i = cb + lane;
        float p0 = 0.f, p1 = 0.f;
        int sv = 0;
        if (i < end) {
            sv = __ldcs(g_ssrc + i);
            float2 elv = *(const float2*)(g_el + 2 * sv);
            float e0 = elv.x + er0; e0 = fmaxf(e0, NEG_SLOPE * e0);
            float e1 = elv.y + er1; e1 = fmaxf(e1, NEG_SLOPE * e1);
            p0 = __expf(e0);
            p1 = __expf(e1);
        }
        s0 += p0; s1 += p1;
        int cnt = min(32, end - cb);
        #pragma unroll 4
        for (int e = 0; e < cnt; e += 2) {
            int eA = e + half16;
            bool valid = eA < cnt;
            int esel = valid ? eA : 0;
            int   ss  = __shfl_sync(0xffffffffu, sv, esel);
            float pp0 = __shfl_sync(0xffffffffu, p0, esel);
            float pp1 = __shfl_sync(0xffffffffu, p1, esel);
            float pp = head ? pp1 : pp0;
            if (!valid) pp = 0.f;
            uint4 v = ftp[(size_t)ss * 16 + l16];
            float2 f0 = __half22float2(*(__half2*)&v.x);
            float2 f1 = __half22float2(*(__half2*)&v.y);
            float2 f2 = __half22float2(*(__half2*)&v.z);
            float2 f3 = __half22float2(*(__half2*)&v.w);
            acc[0] = fmaf(pp, f0.x, acc[0]);
            acc[1] = fmaf(pp, f0.y, acc[1]);
            acc[2] = fmaf(pp, f1.x, acc[2]);
            acc[3] = fmaf(pp, f1.y, acc[3]);
            acc[4] = fmaf(pp, f2.x, acc[4]);
            acc[5] = fmaf(pp, f2.y, acc[5]);
            acc[6] = fmaf(pp, f3.x, acc[6]);
            acc[7] = fmaf(pp, f3.y, acc[7]);
        }
    }

    #pragma unroll
    for (int j = 0; j < 8; j++)
        acc[j] += __shfl_xor_sync(0xffffffffu, acc[j], 16);

    #pragma unroll
    for (int d = 16; d; d >>= 1) {
        s0 += __shfl_xor_sync(0xffffffffu, s0, d);
        s1 += __shfl_xor_sync(0xffffffffu, s1, d);
    }
    float inv = 1.f / fmaxf(head ? s1 : s0, 1e-20f);

    if (half16 == 0) {
        float4* op = (float4*)(out + (size_t)node * HF + l16 * 8);
        __stcs(op,     make_float4(acc[0] * inv, acc[1] * inv, acc[2] * inv, acc[3] * inv));
        __stcs(op + 1, make_float4(acc[4] * inv, acc[5] * inv, acc[6] * inv, acc[7] * inv));
    }
    if (lane == 0) g_deg[node] = 0;   // restore invariant for next call
}

// ===========================================================================
extern "C" void kernel_launch(void* const* d_in, const int* in_sizes, int n_in,
                              void* d_out, int out_size) {
    const float* feat   = (const float*)d_in[0];
    const int*   src    = (const int*)  d_in[1];
    const int*   dst    = (const int*)  d_in[2];
    const float* W      = (const float*)d_in[3];
    const float* attn_l = (const float*)d_in[4];
    const float* attn_r = (const float*)d_in[5];
    float* out = (float*)d_out;

    __half* fth_p; cudaGetSymbolAddress((void**)&fth_p, g_fth);
    float*  el_p;  cudaGetSymbolAddress((void**)&el_p, g_el);
    float*  er_p;  cudaGetSymbolAddress((void**)&er_p, g_er);

    cudaFuncSetAttribute(gemm_mma, cudaFuncAttributeMaxDynamicSharedMemorySize, SM_TOTAL);

    static cudaStream_t s1 = [] {
        cudaStream_t s; cudaStreamCreateWithFlags(&s, cudaStreamNonBlocking); return s;
    }();
    static cudaEvent_t e0 = [] {
        cudaEvent_t e; cudaEventCreateWithFlags(&e, cudaEventDisableTiming); return e;
    }();
    static cudaEvent_t e1 = [] {
        cudaEvent_t e; cudaEventCreateWithFlags(&e, cudaEventDisableTiming); return e;
    }();

    // Fork: GEMM on s1 (independent of bucket build).
    cudaEventRecord(e0, 0);
    cudaStreamWaitEvent(s1, e0, 0);
    gemm_mma<<<(N_NODES + BLOCK_M - 1) / BLOCK_M, 512, SM_TOTAL, s1>>>(
        feat, W, attn_l, attn_r, fth_p, el_p, er_p, N_NODES);
    cudaEventRecord(e1, s1);

    // Main stream: single-pass bucket build (g_deg zero on entry by invariant).
    hist_scatter<<<(N_EDGES / 4 + 255) / 256, 256>>>((const int4*)src, (const int4*)dst);

    // Join, then aggregate.
    cudaStreamWaitEvent(0, e1, 0);
    gat_agg<<<(N_NODES * 32 + 255) / 256, 256>>>(out);
}

// round 16
// speedup vs baseline: 1.1245x; 1.0301x over previous
#include <cuda_runtime.h>
#include <cuda_bf16.h>
#include <cuda_fp16.h>
#include <math.h>
#include <stdint.h>

#define N_NODES 50000
#define N_EDGES 1600000
#define IN_FEATS 256
#define HF 128           // N_HEADS * OUT_FEATS
#define NEG_SLOPE 0.2f
#define EDGE_STRIDE 192  // fixed bucket per node (Poisson(32): P(deg>192) ~ e^-150)
#define BLOCK_M 128

// -------- device scratch --------
__device__ __half g_fth[(size_t)N_NODES * HF];    // projected features fp16
__device__ float g_el[N_NODES * 2];
__device__ float g_er[N_NODES * 2];
__device__ int   g_deg[N_NODES];                  // zero at every call entry (invariant)
__device__ int   g_ssrc[(size_t)N_NODES * EDGE_STRIDE];  // padded per-dst buckets

// ===========================================================================
// helpers
// ===========================================================================
__device__ __forceinline__ uint32_t smem_u32(const void* p) {
    uint32_t a;
    asm("{ .reg .u64 t; cvta.to.shared.u64 t, %1; cvt.u32.u64 %0, t; }" : "=r"(a) : "l"(p));
    return a;
}
__device__ __forceinline__ void ldsm4(uint32_t* r, uint32_t addr) {
    asm volatile("ldmatrix.sync.aligned.m8n8.x4.shared.b16 {%0,%1,%2,%3}, [%4];"
                 : "=r"(r[0]), "=r"(r[1]), "=r"(r[2]), "=r"(r[3]) : "r"(addr));
}
__device__ __forceinline__ void mma16816(float* d, const uint32_t* a, const uint32_t* b) {
    asm volatile("mma.sync.aligned.m16n8k16.row.col.f32.bf16.bf16.f32 "
                 "{%0,%1,%2,%3}, {%4,%5,%6,%7}, {%8,%9}, {%0,%1,%2,%3};"
                 : "+f"(d[0]), "+f"(d[1]), "+f"(d[2]), "+f"(d[3])
                 : "r"(a[0]), "r"(a[1]), "r"(a[2]), "r"(a[3]), "r"(b[0]), "r"(b[1]));
}

// smem: per-buffer layout (64 KB), two buffers (double-buffered K chunks)
#define AHI 0
#define ALO 16384
#define BHI 32768
#define BLO 49152
#define BUFSZ 65536
#define SM_TOTAL (2 * BUFSZ)

// ---- pipeline stage 1: issue A loads into registers (no dependent use) ----
__device__ __forceinline__ void ldg_a(const float* __restrict__ A,
                                      int m0, int M, int tid, int kc,
                                      float2* sa) {
    #pragma unroll
    for (int i = 0; i < 8; i++) {
        int idx = tid + i * 512;          // 4096 = 128 rows x 32 kpairs
        int row = idx >> 5, kp = idx & 31;
        int gr = m0 + row;
        sa[i] = (gr < M) ? __ldcs((const float2*)(A + (size_t)gr * IN_FEATS + kc + kp * 2))
                         : make_float2(0.f, 0.f);
    }
}

// ---- pipeline stage 2: convert+store staged A; load+convert+store W (L2) ----
__device__ __forceinline__ void sts_chunk(const float* __restrict__ W,
                                          int tid, int kc,
                                          const float2* sa, char* sbuf) {
    #pragma unroll
    for (int i = 0; i < 8; i++) {
        int idx = tid + i * 512;
        int row = idx >> 5, kp = idx & 31;
        float2 a = sa[i];
        __nv_bfloat16 hx = __float2bfloat16(a.x), hy = __float2bfloat16(a.y);
        float lx = a.x - __bfloat162float(hx), ly = a.y - __bfloat162float(hy);
        uint32_t off = row * 128 + ((kp * 4) ^ ((row & 7) << 4));
        *(__nv_bfloat162*)(sbuf + AHI + off) = __halves2bfloat162(hx, hy);
        *(__nv_bfloat162*)(sbuf + ALO + off) =
            __halves2bfloat162(__float2bfloat16(lx), __float2bfloat16(ly));
    }
    #pragma unroll
    for (int i = 0; i < 16; i++) {
        int idx = tid + i * 512;          // 8192 = 64 k x 128 n
        int kr = idx >> 7, n = idx & 127;
        float b = __ldg(W + (size_t)(kc + kr) * HF + n);
        __nv_bfloat16 h = __float2bfloat16(b);
        float l = b - __bfloat162float(h);
        uint32_t off = n * 128 + ((kr * 2) ^ ((n & 7) << 4));
        *(__nv_bfloat16*)(sbuf + BHI + off) = h;
        *(__nv_bfloat16*)(sbuf + BLO + off) = __float2bfloat16(l);
    }
}

// ===========================================================================
// Kernel 1: bf16-split mma.sync GEMM, M-tile 128, 512 threads (16 warps),
// register-staged software pipeline: LDG(c+1) -> MMA(c) -> STS(c+1) -> sync.
// Warp layout: 8 row-warps x 16 M, 2 col-warps x 64 N (one head each).
// ===========================================================================
__global__ void __launch_bounds__(512, 1)
gemm_mma(const float* __restrict__ A, const float* __restrict__ W,
         const float* __restrict__ al, const float* __restrict__ ar_,
         __half* __restrict__ fth, float* __restrict__ el, float* __restrict__ er,
         int M) {
    extern __shared__ char smem[];
    const uint32_t sb = smem_u32(smem);
    const int tid = threadIdx.x;
    const int wid = tid >> 5;
    const int lane = tid & 31;
    const int warpRow = wid & 7;    // 8 row-warps of 16 M
    const int warpCol = wid >> 3;   // 2 col-warps of 64 N
    const int m0 = blockIdx.x * BLOCK_M;

    float acc[8][4];
    #pragma unroll
    for (int b = 0; b < 8; b++)
        #pragma unroll
        for (int c = 0; c < 4; c++) acc[b][c] = 0.f;

    float2 sa[8];
    // prologue: chunk 0 straight through
    ldg_a(A, m0, M, tid, 0, sa);
    sts_chunk(W, tid, 0, sa, smem);
    __syncthreads();

    for (int c = 0; c < 4; c++) {
        const uint32_t sbc = sb + (c & 1) * BUFSZ;
        // stage 1: issue next chunk's A loads (latency hides under MMA below)
        if (c < 3) ldg_a(A, m0, M, tid, (c + 1) * 64, sa);

        // stage 2: MMA on current chunk
        #pragma unroll
        for (int ks = 0; ks < 4; ks++) {
            uint32_t ahi[4], alo[4], bh[8][2], bl[8][2];
            {
                int row = warpRow * 16 + (lane & 15);
                int kb = ks * 32 + ((lane >> 4) << 4);
                uint32_t off = row * 128 + (kb ^ ((row & 7) << 4));
                ldsm4(ahi, sbc + AHI + off);
                ldsm4(alo, sbc + ALO + off);
            }
            #pragma unroll
            for (int tp = 0; tp < 4; tp++) {
                int n = warpCol * 64 + tp * 16 + ((lane >> 4) << 3) + (lane & 7);
                int kb = ks * 32 + (((lane >> 3) & 1) << 4);
                uint32_t off = n * 128 + (kb ^ ((n & 7) << 4));
                uint32_t r[4];
                ldsm4(r, sbc + BHI + off);
                bh[tp * 2][0] = r[0]; bh[tp * 2][1] = r[1];
                bh[tp * 2 + 1][0] = r[2]; bh[tp * 2 + 1][1] = r[3];
                ldsm4(r, sbc + BLO + off);
                bl[tp * 2][0] = r[0]; bl[tp * 2][1] = r[1];
                bl[tp * 2 + 1][0] = r[2]; bl[tp * 2 + 1][1] = r[3];
            }
            #pragma unroll
            for (int tn = 0; tn < 8; tn++) {
                mma16816(acc[tn], ahi, bh[tn]);
                mma16816(acc[tn], ahi, bl[tn]);
                mma16816(acc[tn], alo, bh[tn]);
            }
        }

        // stage 3: store next chunk (A from regs; W from L2) into other buffer
        if (c < 3) {
            sts_chunk(W, tid, (c + 1) * 64, sa, smem + ((c + 1) & 1) * BUFSZ);
            __syncthreads();
        }
    }

    // ---- epilogue: fp16 store + fused per-head attention dots ----
    const int qr = lane >> 2, qc = lane & 3;
    #pragma unroll
    for (int h = 0; h < 2; h++) {
        int row = m0 + warpRow * 16 + 8 * h + qr;
        float dotl = 0.f, dotr = 0.f;
        #pragma unroll
        for (int tn = 0; tn < 8; tn++) {
            float v0 = acc[tn][2 * h + 0];
            float v1 = acc[tn][2 * h + 1];
            int col = warpCol * 64 + tn * 8 + qc * 2;
            dotl = fmaf(v0, __ldg(al + col), fmaf(v1, __ldg(al + col + 1), dotl));
            dotr = fmaf(v0, __ldg(ar_ + col), fmaf(v1, __ldg(ar_ + col + 1), dotr));
            if (row < M)
                *(__half2*)(fth + (size_t)row * HF + col) = __floats2half2_rn(v0, v1);
        }
        dotl += __shfl_xor_sync(0xffffffffu, dotl, 1);
        dotl += __shfl_xor_sync(0xffffffffu, dotl, 2);
        dotr += __shfl_xor_sync(0xffffffffu, dotr, 1);
        dotr += __shfl_xor_sync(0xffffffffu, dotr, 2);
        if (qc == 0 && row < M) {
            el[row * 2 + warpCol] = dotl;
            er[row * 2 + warpCol] = dotr;
        }
    }
}

// ===========================================================================
// ONE-pass CSR build into padded buckets.
// ===========================================================================
__global__ void __launch_bounds__(256)
hist_scatter(const int4* __restrict__ src4, const int4* __restrict__ dst4) {
    int i = blockIdx.x * blockDim.x + threadIdx.x;
    if (i < N_EDGES / 4) {
        int4 s = __ldcs(src4 + i);
        int4 d = __ldcs(dst4 + i);
        int r;
        r = atomicAdd(&g_deg[d.x], 1); __stcs(&g_ssrc[(size_t)d.x * EDGE_STRIDE + r], s.x);
        r = atomicAdd(&g_deg[d.y], 1); __stcs(&g_ssrc[(size_t)d.y * EDGE_STRIDE + r], s.y);
        r = atomicAdd(&g_deg[d.z], 1); __stcs(&g_ssrc[(size_t)d.z * EDGE_STRIDE + r], s.z);
        r = atomicAdd(&g_deg[d.w], 1); __stcs(&g_ssrc[(size_t)d.w * EDGE_STRIDE + r], s.w);
    }
}

// ===========================================================================
// warp-per-node softmax + aggregation; resets g_deg afterward.
// ===========================================================================
__global__ void gat_agg(float* __restrict__ out) {
    int gtid = blockIdx.x * blockDim.x + threadIdx.x;
    int node = gtid >> 5;
    int lane = gtid & 31;
    if (node >= N_NODES) return;

    const int deg = g_deg[node];
    const int beg = node * EDGE_STRIDE;
    const int end = beg + deg;
    const float er0 = g_er[node * 2 + 0];
    const float er1 = g_er[node * 2 + 1];
    const int half16 = lane >> 4;
    const int l16 = lane & 15;
    const int head = l16 >> 3;

    const uint4* ftp = (const uint4*)g_fth;
    float acc[8];
    #pragma unroll
    for (int j = 0; j < 8; j++) acc[j] = 0.f;
    float s0 = 0.f, s1 = 0.f;

    for (int cb = beg; cb < end; cb += 32) {
        int i = cb + lane;
        float p0 = 0.f, p1 = 0.f;
        int sv = 0;
        if (i < end) {
            sv = __ldcs(g_ssrc + i);
            float2 elv = *(const float2*)(g_el + 2 * sv);
            float e0 = elv.x + er0; e0 = fmaxf(e0, NEG_SLOPE * e0);
            float e1 = elv.y + er1; e1 = fmaxf(e1, NEG_SLOPE * e1);
            p0 = __expf(e0);
            p1 = __expf(e1);
        }
        s0 += p0; s1 += p1;
        int cnt = min(32, end - cb);
        #pragma unroll 4
        for (int e = 0; e < cnt; e += 2) {
            int eA = e + half16;
            bool valid = eA < cnt;
            int esel = valid ? eA : 0;
            int   ss  = __shfl_sync(0xffffffffu, sv, esel);
            float pp0 = __shfl_sync(0xffffffffu, p0, esel);
            float pp1 = __shfl_sync(0xffffffffu, p1, esel);
            float pp = head ? pp1 : pp0;
            if (!valid) pp = 0.f;
            uint4 v = ftp[(size_t)ss * 16 + l16];
            float2 f0 = __half22float2(*(__half2*)&v.x);
            float2 f1 = __half22float2(*(__half2*)&v.y);
            float2 f2 = __half22float2(*(__half2*)&v.z);
            float2 f3 = __half22float2(*(__half2*)&v.w);
            acc[0] = fmaf(pp, f0.x, acc[0]);
            acc[1] = fmaf(pp, f0.y, acc[1]);
            acc[2] = fmaf(pp, f1.x, acc[2]);
            acc[3] = fmaf(pp, f1.y, acc[3]);
            acc[4] = fmaf(pp, f2.x, acc[4]);
            acc[5] = fmaf(pp, f2.y, acc[5]);
            acc[6] = fmaf(pp, f3.x, acc[6]);
            acc[7] = fmaf(pp, f3.y, acc[7]);
        }
    }

    #pragma unroll
    for (int j = 0; j < 8; j++)
        acc[j] += __shfl_xor_sync(0xffffffffu, acc[j], 16);

    #pragma unroll
    for (int d = 16; d; d >>= 1) {
        s0 += __shfl_xor_sync(0xffffffffu, s0, d);
        s1 += __shfl_xor_sync(0xffffffffu, s1, d);
    }
    float inv = 1.f / fmaxf(head ? s1 : s0, 1e-20f);

    if (half16 == 0) {
        float4* op = (float4*)(out + (size_t)node * HF + l16 * 8);
        __stcs(op,     make_float4(acc[0] * inv, acc[1] * inv, acc[2] * inv, acc[3] * inv));
        __stcs(op + 1, make_float4(acc[4] * inv, acc[5] * inv, acc[6] * inv, acc[7] * inv));
    }
    if (lane == 0) g_deg[node] = 0;   // restore invariant for next call
}

// ===========================================================================
extern "C" void kernel_launch(void* const* d_in, const int* in_sizes, int n_in,
                              void* d_out, int out_size) {
    const float* feat   = (const float*)d_in[0];
    const int*   src    = (const int*)  d_in[1];
    const int*   dst    = (const int*)  d_in[2];
    const float* W      = (const float*)d_in[3];
    const float* attn_l = (const float*)d_in[4];
    const float* attn_r = (const float*)d_in[5];
    float* out = (float*)d_out;

    __half* fth_p; cudaGetSymbolAddress((void**)&fth_p, g_fth);
    float*  el_p;  cudaGetSymbolAddress((void**)&el_p, g_el);
    float*  er_p;  cudaGetSymbolAddress((void**)&er_p, g_er);

    cudaFuncSetAttribute(gemm_mma, cudaFuncAttributeMaxDynamicSharedMemorySize, SM_TOTAL);

    static cudaStream_t s1 = [] {
        cudaStream_t s; cudaStreamCreateWithFlags(&s, cudaStreamNonBlocking); return s;
    }();
    static cudaEvent_t e0 = [] {
        cudaEvent_t e; cudaEventCreateWithFlags(&e, cudaEventDisableTiming); return e;
    }();
    static cudaEvent_t e1 = [] {
        cudaEvent_t e; cudaEventCreateWithFlags(&e, cudaEventDisableTiming); return e;
    }();

    // Fork: GEMM on s1 (independent of bucket build).
    cudaEventRecord(e0, 0);
    cudaStreamWaitEvent(s1, e0, 0);
    gemm_mma<<<(N_NODES + BLOCK_M - 1) / BLOCK_M, 512, SM_TOTAL, s1>>>(
        feat, W, attn_l, attn_r, fth_p, el_p, er_p, N_NODES);
    cudaEventRecord(e1, s1);

    // Main stream: single-pass bucket build (g_deg zero on entry by invariant).
    hist_scatter<<<(N_EDGES / 4 + 255) / 256, 256>>>((const int4*)src, (const int4*)dst);

    // Join, then aggregate.
    cudaStreamWaitEvent(0, e1, 0);
    gat_agg<<<(N_NODES * 32 + 255) / 256, 256>>>(out);
}

// round 17
// speedup vs baseline: 1.1410x; 1.0147x over previous
#include <cuda_runtime.h>
#include <cuda_bf16.h>
#include <cuda_fp16.h>
#include <math.h>
#include <stdint.h>

#define N_NODES 50000
#define N_EDGES 1600000
#define IN_FEATS 256
#define HF 128           // N_HEADS * OUT_FEATS
#define NEG_SLOPE 0.2f
#define EDGE_STRIDE 192  // fixed bucket per node (Poisson(32): P(deg>192) ~ e^-150)
#define BLOCK_M 128

// -------- device scratch --------
__device__ __half g_fth[(size_t)N_NODES * HF];    // projected features fp16
__device__ float g_el[N_NODES * 2];
__device__ float g_er[N_NODES * 2];
__device__ int   g_deg[N_NODES];                  // zero at every call entry (invariant)
__device__ int   g_ssrc[(size_t)N_NODES * EDGE_STRIDE];  // padded per-dst buckets

// ===========================================================================
// helpers
// ===========================================================================
__device__ __forceinline__ uint32_t smem_u32(const void* p) {
    uint32_t a;
    asm("{ .reg .u64 t; cvta.to.shared.u64 t, %1; cvt.u32.u64 %0, t; }" : "=r"(a) : "l"(p));
    return a;
}
__device__ __forceinline__ void ldsm4(uint32_t* r, uint32_t addr) {
    asm volatile("ldmatrix.sync.aligned.m8n8.x4.shared.b16 {%0,%1,%2,%3}, [%4];"
                 : "=r"(r[0]), "=r"(r[1]), "=r"(r[2]), "=r"(r[3]) : "r"(addr));
}
__device__ __forceinline__ void mma16816(float* d, const uint32_t* a, const uint32_t* b) {
    asm volatile("mma.sync.aligned.m16n8k16.row.col.f32.bf16.bf16.f32 "
                 "{%0,%1,%2,%3}, {%4,%5,%6,%7}, {%8,%9}, {%0,%1,%2,%3};"
                 : "+f"(d[0]), "+f"(d[1]), "+f"(d[2]), "+f"(d[3])
                 : "r"(a[0]), "r"(a[1]), "r"(a[2]), "r"(a[3]), "r"(b[0]), "r"(b[1]));
}

// smem: per-buffer layout (64 KB), two buffers (double-buffered K chunks)
#define AHI 0
#define ALO 16384
#define BHI 32768
#define BLO 49152
#define BUFSZ 65536
#define SM_TOTAL (2 * BUFSZ)

// ---- pipeline stage 1: issue A loads into registers ----
__device__ __forceinline__ void ldg_a(const float* __restrict__ A,
                                      int m0, int M, int tid, int kc,
                                      float2* sa) {
    #pragma unroll
    for (int i = 0; i < 8; i++) {
        int idx = tid + i * 512;          // 4096 = 128 rows x 32 kpairs
        int row = idx >> 5, kp = idx & 31;
        int gr = m0 + row;
        sa[i] = (gr < M) ? __ldcs((const float2*)(A + (size_t)gr * IN_FEATS + kc + kp * 2))
                         : make_float2(0.f, 0.f);
    }
}

// ---- pipeline stage 2: convert+store staged A; load+convert+store W ----
__device__ __forceinline__ void sts_chunk(const float* __restrict__ W,
                                          int tid, int kc,
                                          const float2* sa, char* sbuf) {
    #pragma unroll
    for (int i = 0; i < 8; i++) {
        int idx = tid + i * 512;
        int row = idx >> 5, kp = idx & 31;
        float2 a = sa[i];
        __nv_bfloat16 hx = __float2bfloat16(a.x), hy = __float2bfloat16(a.y);
        float lx = a.x - __bfloat162float(hx), ly = a.y - __bfloat162float(hy);
        uint32_t off = row * 128 + ((kp * 4) ^ ((row & 7) << 4));
        *(__nv_bfloat162*)(sbuf + AHI + off) = __halves2bfloat162(hx, hy);
        *(__nv_bfloat162*)(sbuf + ALO + off) =
            __halves2bfloat162(__float2bfloat16(lx), __float2bfloat16(ly));
    }
    #pragma unroll
    for (int i = 0; i < 16; i++) {
        int idx = tid + i * 512;          // 8192 = 64 k x 128 n
        int kr = idx >> 7, n = idx & 127;
        float b = __ldg(W + (size_t)(kc + kr) * HF + n);
        __nv_bfloat16 h = __float2bfloat16(b);
        float l = b - __bfloat162float(h);
        uint32_t off = n * 128 + ((kr * 2) ^ ((n & 7) << 4));
        *(__nv_bfloat16*)(sbuf + BHI + off) = h;
        *(__nv_bfloat16*)(sbuf + BLO + off) = __float2bfloat16(l);
    }
}

// ===========================================================================
// Kernel 1: bf16-split mma.sync GEMM, M-tile 128, 512 threads (16 warps),
// register-staged pipeline, 4x4 warp layout (balanced ldsm duplication):
// 4 row-warps x 32 M, 4 col-warps x 32 N.
// ===========================================================================
__global__ void __launch_bounds__(512, 1)
gemm_mma(const float* __restrict__ A, const float* __restrict__ W,
         const float* __restrict__ al, const float* __restrict__ ar_,
         __half* __restrict__ fth, float* __restrict__ el, float* __restrict__ er,
         int M) {
    extern __shared__ char smem[];
    const uint32_t sb = smem_u32(smem);
    const int tid = threadIdx.x;
    const int wid = tid >> 5;
    const int lane = tid & 31;
    const int warpRow = wid & 3;    // 4 row-warps of 32 M
    const int warpCol = wid >> 2;   // 4 col-warps of 32 N
    const int m0 = blockIdx.x * BLOCK_M;

    float acc[2][4][4];
    #pragma unroll
    for (int a = 0; a < 2; a++)
        #pragma unroll
        for (int b = 0; b < 4; b++)
            #pragma unroll
            for (int c = 0; c < 4; c++) acc[a][b][c] = 0.f;

    float2 sa[8];
    ldg_a(A, m0, M, tid, 0, sa);
    sts_chunk(W, tid, 0, sa, smem);
    __syncthreads();

    for (int c = 0; c < 4; c++) {
        const uint32_t sbc = sb + (c & 1) * BUFSZ;
        if (c < 3) ldg_a(A, m0, M, tid, (c + 1) * 64, sa);

        #pragma unroll
        for (int ks = 0; ks < 4; ks++) {
            uint32_t ahi[2][4], alo[2][4], bh[4][2], bl[4][2];
            #pragma unroll
            for (int tm = 0; tm < 2; tm++) {
                int row = warpRow * 32 + tm * 16 + (lane & 15);
                int kb = ks * 32 + ((lane >> 4) << 4);
                uint32_t off = row * 128 + (kb ^ ((row & 7) << 4));
                ldsm4(ahi[tm], sbc + AHI + off);
                ldsm4(alo[tm], sbc + ALO + off);
            }
            #pragma unroll
            for (int tp = 0; tp < 2; tp++) {
                int n = warpCol * 32 + tp * 16 + ((lane >> 4) << 3) + (lane & 7);
                int kb = ks * 32 + (((lane >> 3) & 1) << 4);
                uint32_t off = n * 128 + (kb ^ ((n & 7) << 4));
                uint32_t r[4];
                ldsm4(r, sbc + BHI + off);
                bh[tp * 2][0] = r[0]; bh[tp * 2][1] = r[1];
                bh[tp * 2 + 1][0] = r[2]; bh[tp * 2 + 1][1] = r[3];
                ldsm4(r, sbc + BLO + off);
                bl[tp * 2][0] = r[0]; bl[tp * 2][1] = r[1];
                bl[tp * 2 + 1][0] = r[2]; bl[tp * 2 + 1][1] = r[3];
            }
            #pragma unroll
            for (int tm = 0; tm < 2; tm++)
                #pragma unroll
                for (int tn = 0; tn < 4; tn++) {
                    mma16816(acc[tm][tn], ahi[tm], bh[tn]);
                    mma16816(acc[tm][tn], ahi[tm], bl[tn]);
                    mma16816(acc[tm][tn], alo[tm], bh[tn]);
                }
        }

        if (c < 3) {
            sts_chunk(W, tid, (c + 1) * 64, sa, smem + ((c + 1) & 1) * BUFSZ);
        }
        __syncthreads();
    }

    // ---- epilogue: fp16 store + per-head attention dots via smem combine ----
    // red[warpCol][128 rows][2] floats = 4 KB, overlays buffer 0 (post-sync).
    float* red = (float*)smem;
    const int qr = lane >> 2, qc = lane & 3;
    #pragma unroll
    for (int tm = 0; tm < 2; tm++) {
        #pragma unroll
        for (int h = 0; h < 2; h++) {
            int lrow = warpRow * 32 + tm * 16 + 8 * h + qr;   // 0..127
            int grow = m0 + lrow;
            float dotl = 0.f, dotr = 0.f;
            #pragma unroll
            for (int tn = 0; tn < 4; tn++) {
                float v0 = acc[tm][tn][2 * h + 0];
                float v1 = acc[tm][tn][2 * h + 1];
                int col = warpCol * 32 + tn * 8 + qc * 2;
                dotl = fmaf(v0, __ldg(al + col), fmaf(v1, __ldg(al + col + 1), dotl));
                dotr = fmaf(v0, __ldg(ar_ + col), fmaf(v1, __ldg(ar_ + col + 1), dotr));
                if (grow < M)
                    *(__half2*)(fth + (size_t)grow * HF + col) = __floats2half2_rn(v0, v1);
            }
            dotl += __shfl_xor_sync(0xffffffffu, dotl, 1);
            dotl += __shfl_xor_sync(0xffffffffu, dotl, 2);
            dotr += __shfl_xor_sync(0xffffffffu, dotr, 1);
            dotr += __shfl_xor_sync(0xffffffffu, dotr, 2);
            if (qc == 0) {
                red[(warpCol * 128 + lrow) * 2 + 0] = dotl;
                red[(warpCol * 128 + lrow) * 2 + 1] = dotr;
            }
        }
    }
    __syncthreads();
    // combine col-warp pairs: head0 = wc0+wc1, head1 = wc2+wc3.
    // 512 threads cover 128 rows x 2 heads x 2 (l/r).
    {
        int lrow = tid >> 2;
        int head = (tid >> 1) & 1;
        int lr = tid & 1;
        float v = red[((head * 2 + 0) * 128 + lrow) * 2 + lr]
                + red[((head * 2 + 1) * 128 + lrow) * 2 + lr];
        int grow = m0 + lrow;
        if (grow < M) {
            if (lr) er[grow * 2 + head] = v;
            else    el[grow * 2 + head] = v;
        }
    }
}

// ===========================================================================
// ONE-pass CSR build into padded buckets.
// ===========================================================================
__global__ void __launch_bounds__(256)
hist_scatter(const int4* __restrict__ src4, const int4* __restrict__ dst4) {
    int i = blockIdx.x * blockDim.x + threadIdx.x;
    if (i < N_EDGES / 4) {
        int4 s = __ldcs(src4 + i);
        int4 d = __ldcs(dst4 + i);
        int r;
        r = atomicAdd(&g_deg[d.x], 1); __stcs(&g_ssrc[(size_t)d.x * EDGE_STRIDE + r], s.x);
        r = atomicAdd(&g_deg[d.y], 1); __stcs(&g_ssrc[(size_t)d.y * EDGE_STRIDE + r], s.y);
        r = atomicAdd(&g_deg[d.z], 1); __stcs(&g_ssrc[(size_t)d.z * EDGE_STRIDE + r], s.z);
        r = atomicAdd(&g_deg[d.w], 1); __stcs(&g_ssrc[(size_t)d.w * EDGE_STRIDE + r], s.w);
    }
}

// ===========================================================================
// warp-per-node softmax + aggregation; resets g_deg afterward.
// ===========================================================================
__global__ void gat_agg(float* __restrict__ out) {
    int gtid = blockIdx.x * blockDim.x + threadIdx.x;
    int node = gtid >> 5;
    int lane = gtid & 31;
    if (node >= N_NODES) return;

    const int deg = g_deg[node];
    const int beg = node * EDGE_STRIDE;
    const int end = beg + deg;
    const float er0 = g_er[node * 2 + 0];
    const float er1 = g_er[node * 2 + 1];
    const int half16 = lane >> 4;
    const int l16 = lane & 15;
    const int head = l16 >> 3;

    const uint4* ftp = (const uint4*)g_fth;
    float acc[8];
    #pragma unroll
    for (int j = 0; j < 8; j++) acc[j] = 0.f;
    float s0 = 0.f, s1 = 0.f;

    for (int cb = beg; cb < end; cb += 32) {
        int i = cb + lane;
        float p0 = 0.f, p1 = 0.f;
        int sv = 0;
        if (i < end) {
            sv = __ldcs(g_ssrc + i);
            float2 elv = *(const float2*)(g_el + 2 * sv);
            float e0 = elv.x + er0; e0 = fmaxf(e0, NEG_SLOPE * e0);
            float e1 = elv.y + er1; e1 = fmaxf(e1, NEG_SLOPE * e1);
            p0 = __expf(e0);
            p1 = __expf(e1);
        }
        s0 += p0; s1 += p1;
        int cnt = min(32, end - cb);
        #pragma unroll 4
        for (int e = 0; e < cnt; e += 2) {
            int eA = e + half16;
            bool valid = eA < cnt;
            int esel = valid ? eA : 0;
            int   ss  = __shfl_sync(0xffffffffu, sv, esel);
            float pp0 = __shfl_sync(0xffffffffu, p0, esel);
            float pp1 = __shfl_sync(0xffffffffu, p1, esel);
            float pp = head ? pp1 : pp0;
            if (!valid) pp = 0.f;
            uint4 v = ftp[(size_t)ss * 16 + l16];
            float2 f0 = __half22float2(*(__half2*)&v.x);
            float2 f1 = __half22float2(*(__half2*)&v.y);
            float2 f2 = __half22float2(*(__half2*)&v.z);
            float2 f3 = __half22float2(*(__half2*)&v.w);
            acc[0] = fmaf(pp, f0.x, acc[0]);
            acc[1] = fmaf(pp, f0.y, acc[1]);
            acc[2] = fmaf(pp, f1.x, acc[2]);
            acc[3] = fmaf(pp, f1.y, acc[3]);
            acc[4] = fmaf(pp, f2.x, acc[4]);
            acc[5] = fmaf(pp, f2.y, acc[5]);
            acc[6] = fmaf(pp, f3.x, acc[6]);
            acc[7] = fmaf(pp, f3.y, acc[7]);
        }
    }

    #pragma unroll
    for (int j = 0; j < 8; j++)
        acc[j] += __shfl_xor_sync(0xffffffffu, acc[j], 16);

    #pragma unroll
    for (int d = 16; d; d >>= 1) {
        s0 += __shfl_xor_sync(0xffffffffu, s0, d);
        s1 += __shfl_xor_sync(0xffffffffu, s1, d);
    }
    float inv = 1.f / fmaxf(head ? s1 : s0, 1e-20f);

    if (half16 == 0) {
        float4* op = (float4*)(out + (size_t)node * HF + l16 * 8);
        __stcs(op,     make_float4(acc[0] * inv, acc[1] * inv, acc[2] * inv, acc[3] * inv));
        __stcs(op + 1, make_float4(acc[4] * inv, acc[5] * inv, acc[6] * inv, acc[7] * inv));
    }
    if (lane == 0) g_deg[node] = 0;   // restore invariant for next call
}

// ===========================================================================
extern "C" void kernel_launch(void* const* d_in, const int* in_sizes, int n_in,
                              void* d_out, int out_size) {
    const float* feat   = (const float*)d_in[0];
    const int*   src    = (const int*)  d_in[1];
    const int*   dst    = (const int*)  d_in[2];
    const float* W      = (const float*)d_in[3];
    const float* attn_l = (const float*)d_in[4];
    const float* attn_r = (const float*)d_in[5];
    float* out = (float*)d_out;

    __half* fth_p; cudaGetSymbolAddress((void**)&fth_p, g_fth);
    float*  el_p;  cudaGetSymbolAddress((void**)&el_p, g_el);
    float*  er_p;  cudaGetSymbolAddress((void**)&er_p, g_er);

    cudaFuncSetAttribute(gemm_mma, cudaFuncAttributeMaxDynamicSharedMemorySize, SM_TOTAL);

    static cudaStream_t s1 = [] {
        cudaStream_t s; cudaStreamCreateWithFlags(&s, cudaStreamNonBlocking); return s;
    }();
    static cudaEvent_t e0 = [] {
        cudaEvent_t e; cudaEventCreateWithFlags(&e, cudaEventDisableTiming); return e;
    }();
    static cudaEvent_t e1 = [] {
        cudaEvent_t e; cudaEventCreateWithFlags(&e, cudaEventDisableTiming); return e;
    }();

    // Fork: GEMM on s1 (independent of bucket build).
    cudaEventRecord(e0, 0);
    cudaStreamWaitEvent(s1, e0, 0);
    gemm_mma<<<(N_NODES + BLOCK_M - 1) / BLOCK_M, 512, SM_TOTAL, s1>>>(
        feat, W, attn_l, attn_r, fth_p, el_p, er_p, N_NODES);
    cudaEventRecord(e1, s1);

    // Main stream: single-pass bucket build (g_deg zero on entry by invariant).
    hist_scatter<<<(N_EDGES / 4 + 255) / 256, 256>>>((const int4*)src, (const int4*)dst);

    // Join, then aggregate.
    cudaStreamWaitEvent(0, e1, 0);
    gat_agg<<<(N_NODES * 32 + 255) / 256, 256>>>(out);
}